// round 6
// baseline (speedup 1.0000x reference)
#include <cuda_runtime.h>
#include <math.h>

#define BB 256   // batch
#define NS 32    // spans
#define DD 512   // feature dim

#define TR 2     // rows per block tile
#define TC 64    // cols per block tile (16 col-groups x 4 cols via float4)
#define NQ 32    // K-split factor within block (16 k's per split)

// Scratch (allocation-free rule: __device__ globals)
__device__ float g_A[BB * DD];        // ner span-sums, [b][d], pre-scaled by 1/1024
__device__ float g_FT[DD * BB];       // face span-sums, TRANSPOSED [d][c]
__device__ float g_rowsum[BB];        // per-row sum(exp(logits))
__device__ float g_diagv[BB];         // logits[b][b]
__device__ unsigned int g_cnt;        // block arrival counter

// ---------------------------------------------------------------------------
// Kernel 1: span reductions. 512 blocks x 512 threads.
// Thread = (d4, span-group). 4 partial sums combined in shared memory.
// Also zeroes the kernel-2 accumulators (runs strictly before kernel 2).
// ---------------------------------------------------------------------------
__global__ void reduce_spans(const float* __restrict__ face,
                             const float* __restrict__ ner) {
    const int blk = blockIdx.x;
    const int tid = threadIdx.x;
    const int t4  = tid & 127;     // float4 index within row (128 * 4 = 512 d)
    const int grp = tid >> 7;      // span group 0..3 (8 spans each)

    if (blk == 0) {
        if (tid < BB) g_rowsum[tid] = 0.f;
        if (tid == BB) g_cnt = 0u;
    }

    const bool is_ner = (blk < BB);
    const int row = is_ner ? blk : blk - BB;
    const float4* src = reinterpret_cast<const float4*>(
        (is_ner ? ner : face) + (size_t)row * NS * DD);

    float4 s = make_float4(0.f, 0.f, 0.f, 0.f);
#pragma unroll
    for (int n = 0; n < 8; n++) {
        float4 v = src[(grp * 8 + n) * (DD / 4) + t4];
        s.x += v.x; s.y += v.y; s.z += v.z; s.w += v.w;
    }

    __shared__ float4 sp[3][128];
    if (grp > 0) sp[grp - 1][t4] = s;
    __syncthreads();

    if (grp == 0) {
#pragma unroll
        for (int i = 0; i < 3; i++) {
            float4 v = sp[i][t4];
            s.x += v.x; s.y += v.y; s.z += v.z; s.w += v.w;
        }
        if (is_ner) {
            const float inv = 1.0f / 1024.0f;   // fold the 1/(N1*N2) mean
            s.x *= inv; s.y *= inv; s.z *= inv; s.w *= inv;
            reinterpret_cast<float4*>(g_A + row * DD)[t4] = s;
        } else {
            const int d = t4 * 4;
            g_FT[(d + 0) * BB + row] = s.x;
            g_FT[(d + 1) * BB + row] = s.y;
            g_FT[(d + 2) * BB + row] = s.z;
            g_FT[(d + 3) * BB + row] = s.w;
        }
    }
}

// ---------------------------------------------------------------------------
// Kernel 2: tiled GEMM (2 rows x 64 cols per block, k-split 32) + fused
// no-max softmax row-sums via atomics + last-block finalize.
// grid = 512 blocks x 512 THREADS (262K threads -> ~14 warps/SMSP).
// Thread = (cl = tid&15 -> 4 cols via float4, q = tid>>4 -> 16 k's).
// Inner loop: 1 LDG.128 (FT, 4 cols) + 1 broadcast LDS.64 (2 A rows) + 8 FMA.
// ---------------------------------------------------------------------------
__global__ void __launch_bounds__(512, 3) gemm_lse(float* __restrict__ out) {
    const int bx = blockIdx.x;
    const int row_tile = bx >> 2;        // 0..127
    const int col_tile = bx & 3;         // 0..3 (same-SM blocks share: 148%4==0)
    const int r0 = row_tile * TR;
    const int c0 = col_tile * TC;
    const int tid = threadIdx.x;
    const int cl  = tid & 15;            // col group (4 cols)
    const int q   = tid >> 4;            // k-split 0..31
    const int c   = c0 + cl * 4;         // first of 4 global cols

    // A tile, transposed: sAT[k][r] (k-major, 2 rows contiguous -> LDS.64)
    __shared__ float sAT[DD * TR];       // 4 KB
    if (tid < 256) {                     // 256 float4 slots, coalesced
        const int r  = tid >> 7;         // 0..1
        const int k4 = tid & 127;        // float4 index along k
        const float4 v = reinterpret_cast<const float4*>(
            g_A + (r0 + r) * DD)[k4];
        sAT[(k4 * 4 + 0) * TR + r] = v.x;
        sAT[(k4 * 4 + 1) * TR + r] = v.y;
        sAT[(k4 * 4 + 2) * TR + r] = v.z;
        sAT[(k4 * 4 + 3) * TR + r] = v.w;
    }
    __syncthreads();

    float acc[TR][4];
#pragma unroll
    for (int r = 0; r < TR; r++)
#pragma unroll
        for (int j = 0; j < 4; j++) acc[r][j] = 0.f;

    const int kbase = q * (DD / NQ);     // 16 k's per split
#pragma unroll
    for (int kk = 0; kk < DD / NQ; kk++) {
        const int k = kbase + kk;
        const float4 f = *reinterpret_cast<const float4*>(g_FT + k * BB + c);
        const float2 a = *reinterpret_cast<const float2*>(sAT + k * TR);
        acc[0][0] = fmaf(a.x, f.x, acc[0][0]);
        acc[0][1] = fmaf(a.x, f.y, acc[0][1]);
        acc[0][2] = fmaf(a.x, f.z, acc[0][2]);
        acc[0][3] = fmaf(a.x, f.w, acc[0][3]);
        acc[1][0] = fmaf(a.y, f.x, acc[1][0]);
        acc[1][1] = fmaf(a.y, f.y, acc[1][1]);
        acc[1][2] = fmaf(a.y, f.z, acc[1][2]);
        acc[1][3] = fmaf(a.y, f.w, acc[1][3]);
    }

    // combine k-splits: sP[q][cl][8 accs + pad]
    __shared__ float sP[NQ][16][TR * 4 + 1];   // 18.4 KB
#pragma unroll
    for (int r = 0; r < TR; r++)
#pragma unroll
        for (int j = 0; j < 4; j++) sP[q][cl][r * 4 + j] = acc[r][j];
    __syncthreads();

    // threads 0..127: thread owns logits[r0+r2][c0+c2l]
    if (tid < TR * TC) {                 // 128
        const int r2  = tid >> 6;        // 0..1
        const int c2l = tid & 63;        // 0..63
        const int clo = c2l >> 2;
        const int jj  = c2l & 3;
        float l = 0.f;
#pragma unroll
        for (int qq = 0; qq < NQ; qq++) l += sP[qq][clo][r2 * 4 + jj];

        if (c0 + c2l == r0 + r2) g_diagv[r0 + r2] = l;

        // per-row partial sum(exp): 2 warps per row, warp-reduce + atomic
        float e = __expf(l);
#pragma unroll
        for (int o = 16; o; o >>= 1) e += __shfl_xor_sync(0xffffffffu, e, o);
        if ((tid & 31) == 0) atomicAdd(&g_rowsum[r0 + r2], e);
    }

    // ---- last-arriving block finalizes ----
    __shared__ unsigned int arrival;
    __syncthreads();                     // all atomics of this block issued
    if (tid == 0) {
        __threadfence();
        arrival = atomicAdd(&g_cnt, 1u);
    }
    __syncthreads();

    if (arrival == 511u && tid < 256) {
        __threadfence();
        volatile float* vs = g_rowsum;
        volatile float* vd = g_diagv;
        float v = vd[tid] - logf(vs[tid]);   // logp[b][b]
        const int lane = tid & 31;
        const int warp = tid >> 5;
        __shared__ float red[8];
#pragma unroll
        for (int o = 16; o; o >>= 1) v += __shfl_xor_sync(0xffffffffu, v, o);
        if (lane == 0) red[warp] = v;
        __syncthreads();
        if (tid == 0) {
            float s = red[0];
#pragma unroll
            for (int i = 1; i < 8; i++) s += red[i];
            out[0] = -s * (1.0f / 256.0f);
        }
    }
}

extern "C" void kernel_launch(void* const* d_in, const int* in_sizes, int n_in,
                              void* d_out, int out_size) {
    const float* face = (const float*)d_in[0];  // (256, 32, 512)
    const float* ner  = (const float*)d_in[1];  // (256, 32, 512)
    float* out = (float*)d_out;

    reduce_spans<<<2 * BB, 512>>>(face, ner);
    gemm_lse<<<512, 512>>>(out);
}

// round 7
// speedup vs baseline: 1.2633x; 1.2633x over previous
#include <cuda_runtime.h>
#include <math.h>

#define BB 256   // batch
#define NS 32    // spans
#define DD 512   // feature dim

#define TR 2     // rows per block tile
#define TC 64    // cols per block tile (16 col-groups x 4 cols via float4)
#define NQ 16    // K-split factor within block (32 k's per split)

// Scratch (allocation-free rule: __device__ globals)
__device__ float g_A[BB * DD];        // ner span-sums, [b][d], pre-scaled by 1/1024
__device__ float g_FT[DD * BB];       // face span-sums, TRANSPOSED [d][c]
__device__ float g_rowsum[BB];        // per-row sum(exp(logits))
__device__ float g_diagv[BB];         // logits[b][b]
__device__ unsigned int g_cnt;        // block arrival counter

// ---------------------------------------------------------------------------
// Kernel 1: span reductions. 512 blocks x 512 threads.
// Thread = (d4, span-group). 4 partial sums combined in shared memory.
// Also zeroes the kernel-2 accumulators (runs strictly before kernel 2).
// ---------------------------------------------------------------------------
__global__ void reduce_spans(const float* __restrict__ face,
                             const float* __restrict__ ner) {
    const int blk = blockIdx.x;
    const int tid = threadIdx.x;
    const int t4  = tid & 127;     // float4 index within row (128 * 4 = 512 d)
    const int grp = tid >> 7;      // span group 0..3 (8 spans each)

    if (blk == 0) {
        if (tid < BB) g_rowsum[tid] = 0.f;
        if (tid == BB) g_cnt = 0u;
    }

    const bool is_ner = (blk < BB);
    const int row = is_ner ? blk : blk - BB;
    const float4* src = reinterpret_cast<const float4*>(
        (is_ner ? ner : face) + (size_t)row * NS * DD);

    float4 s = make_float4(0.f, 0.f, 0.f, 0.f);
#pragma unroll
    for (int n = 0; n < 8; n++) {
        float4 v = src[(grp * 8 + n) * (DD / 4) + t4];
        s.x += v.x; s.y += v.y; s.z += v.z; s.w += v.w;
    }

    __shared__ float4 sp[3][128];
    if (grp > 0) sp[grp - 1][t4] = s;
    __syncthreads();

    if (grp == 0) {
#pragma unroll
        for (int i = 0; i < 3; i++) {
            float4 v = sp[i][t4];
            s.x += v.x; s.y += v.y; s.z += v.z; s.w += v.w;
        }
        if (is_ner) {
            const float inv = 1.0f / 1024.0f;   // fold the 1/(N1*N2) mean
            s.x *= inv; s.y *= inv; s.z *= inv; s.w *= inv;
            reinterpret_cast<float4*>(g_A + row * DD)[t4] = s;
        } else {
            const int d = t4 * 4;
            g_FT[(d + 0) * BB + row] = s.x;
            g_FT[(d + 1) * BB + row] = s.y;
            g_FT[(d + 2) * BB + row] = s.z;
            g_FT[(d + 3) * BB + row] = s.w;
        }
    }
}

// ---------------------------------------------------------------------------
// Kernel 2: tiled GEMM (2 rows x 64 cols per block, k-split 16) + fused
// no-max softmax row-sums via atomics + last-block finalize.
// grid = 512 blocks x 256 threads. Thread = (cl = tid&15 -> 4 cols via
// float4, q = tid>>4 -> 32 k's). Mainloop is 8-DEEP LOAD-BATCHED:
//   8 back-to-back LDG.128 (FT) -> f[8], then 8 x (LDS.64 + 8 FMA).
// One exposed scoreboard wait per 8 loads -> MLP ~8 per thread.
// ---------------------------------------------------------------------------
__global__ void gemm_lse(float* __restrict__ out) {
    const int bx = blockIdx.x;
    const int row_tile = bx >> 2;        // 0..127
    const int col_tile = bx & 3;         // 0..3 (same SM across waves: 148%4==0)
    const int r0 = row_tile * TR;
    const int c0 = col_tile * TC;
    const int tid = threadIdx.x;
    const int cl  = tid & 15;            // col group (4 cols)
    const int q   = tid >> 4;            // k-split 0..15
    const int c   = c0 + cl * 4;         // first of 4 global cols

    // A tile, transposed: sAT[k][r] (k-major, 2 rows contiguous -> LDS.64)
    __shared__ float sAT[DD * TR];       // 4 KB
    {
        const int r  = tid >> 7;          // 0..1
        const int k4 = tid & 127;         // float4 index along k
        const float4 v = reinterpret_cast<const float4*>(
            g_A + (r0 + r) * DD)[k4];
        sAT[(k4 * 4 + 0) * TR + r] = v.x;
        sAT[(k4 * 4 + 1) * TR + r] = v.y;
        sAT[(k4 * 4 + 2) * TR + r] = v.z;
        sAT[(k4 * 4 + 3) * TR + r] = v.w;
    }
    __syncthreads();

    float acc[TR][4];
#pragma unroll
    for (int r = 0; r < TR; r++)
#pragma unroll
        for (int j = 0; j < 4; j++) acc[r][j] = 0.f;

    const int kbase = q * (DD / NQ);     // 32 k's per split
#pragma unroll
    for (int b = 0; b < 4; b++) {        // 4 batches of 8 k's
        const int k0 = kbase + b * 8;
        float4 f[8];
#pragma unroll
        for (int i = 0; i < 8; i++)      // 8 independent LDG.128 in flight
            f[i] = *reinterpret_cast<const float4*>(g_FT + (k0 + i) * BB + c);
#pragma unroll
        for (int i = 0; i < 8; i++) {
            const float2 a = *reinterpret_cast<const float2*>(sAT + (k0 + i) * TR);
            acc[0][0] = fmaf(a.x, f[i].x, acc[0][0]);
            acc[0][1] = fmaf(a.x, f[i].y, acc[0][1]);
            acc[0][2] = fmaf(a.x, f[i].z, acc[0][2]);
            acc[0][3] = fmaf(a.x, f[i].w, acc[0][3]);
            acc[1][0] = fmaf(a.y, f[i].x, acc[1][0]);
            acc[1][1] = fmaf(a.y, f[i].y, acc[1][1]);
            acc[1][2] = fmaf(a.y, f[i].z, acc[1][2]);
            acc[1][3] = fmaf(a.y, f[i].w, acc[1][3]);
        }
    }

    // combine k-splits: sP[q][cl][8 accs + pad]
    __shared__ float sP[NQ][16][TR * 4 + 1];   // ~9.2 KB
#pragma unroll
    for (int r = 0; r < TR; r++)
#pragma unroll
        for (int j = 0; j < 4; j++) sP[q][cl][r * 4 + j] = acc[r][j];
    __syncthreads();

    // threads 0..127: thread owns logits[r0+r2][c0+c2l]
    if (tid < TR * TC) {                 // 128
        const int r2  = tid >> 6;        // 0..1
        const int c2l = tid & 63;        // 0..63
        const int clo = c2l >> 2;
        const int jj  = c2l & 3;
        float l = 0.f;
#pragma unroll
        for (int qq = 0; qq < NQ; qq++) l += sP[qq][clo][r2 * 4 + jj];

        if (c0 + c2l == r0 + r2) g_diagv[r0 + r2] = l;

        // per-row partial sum(exp): 2 warps per row, warp-reduce + atomic
        float e = __expf(l);
#pragma unroll
        for (int o = 16; o; o >>= 1) e += __shfl_xor_sync(0xffffffffu, e, o);
        if ((tid & 31) == 0) atomicAdd(&g_rowsum[r0 + r2], e);
    }

    // ---- last-arriving block finalizes ----
    __shared__ unsigned int arrival;
    __syncthreads();                     // all atomics of this block issued
    if (tid == 0) {
        __threadfence();
        arrival = atomicAdd(&g_cnt, 1u);
    }
    __syncthreads();

    if (arrival == 511u) {
        __threadfence();
        volatile float* vs = g_rowsum;
        volatile float* vd = g_diagv;
        float v = vd[tid] - logf(vs[tid]);   // logp[b][b]
        const int lane = tid & 31;
        const int warp = tid >> 5;
        __shared__ float red[8];
#pragma unroll
        for (int o = 16; o; o >>= 1) v += __shfl_xor_sync(0xffffffffu, v, o);
        if (lane == 0) red[warp] = v;
        __syncthreads();
        if (tid == 0) {
            float s = red[0];
#pragma unroll
            for (int i = 1; i < 8; i++) s += red[i];
            out[0] = -s * (1.0f / 256.0f);
        }
    }
}

extern "C" void kernel_launch(void* const* d_in, const int* in_sizes, int n_in,
                              void* d_out, int out_size) {
    const float* face = (const float*)d_in[0];  // (256, 32, 512)
    const float* ner  = (const float*)d_in[1];  // (256, 32, 512)
    float* out = (float*)d_out;

    reduce_spans<<<2 * BB, 512>>>(face, ner);
    gemm_lse<<<512, 256>>>(out);
}